// round 5
// baseline (speedup 1.0000x reference)
#include <cuda_runtime.h>
#include <stdint.h>

#define KOUT 49
#define MAXT 32
#define SAMPLES_PER_BLK 32
#define THREADS_PER_BLK 224        // 7 warps: warp w -> mu = w, lane -> sample
#define GMAX 16                    // group slots per mu (overflow-safe)
#define KPAD 4                     // padded terms per group (physics bound: <=4)
#define XSTR 116                   // words/lane blob: X1 rows 7x8 (0..55), X2 rows 7x8 (56..111), pad 4
                                   // 116 = 4*29 -> 16B-aligned lane bases, conflict-free LDS.128
#define X2BASE_B 224               // byte offset of X2 row 0 within lane blob (56 words)
#define OBASE (SAMPLES_PER_BLK * XSTR)      // 3712 words
#define OUTSTR 33
#define SMEM_WORDS (OBASE + KOUT * OUTSTR)  // 5329 words = 21316 B

// ---- device tables built by setup kernel each launch ----
__device__ int      g_G[8];                  // stage-1 group counts per mu
__device__ unsigned g_ghdr[7 * GMAX];        // per (mu,g): X2-row byte offset in lane blob
__device__ uint2    g_gterm[7 * GMAX * KPAD];// per (mu,g,k): {X1-row byteoff, c bits}; c=0 pad
__device__ float    g_D[KOUT * 8];           // dense stage-2: D[i][mup], i=m1p*7+m2p, padded to 8

// ---------------------------------------------------------------------------
// Setup: recover factorized term lists from the aligned product arrays.
// Generation order is (mu, t, mup, t'):
//   focc[v] (v<7) -> start of (mu=0,t=0,mup=v) run ; focc[mu*7] -> mu segment
//   T[v] = focc[v+1]-focc[v] (v<6); T[6] = focc[7]/T[0] - focc[6]; Ttot = focc[6]+T[6]
// Coefficients from products only (A = mult[0] = c0^2):
//   c_hat(mu,t)   = mult[seg(mu) + t*Ttot]   (= c_t * c0)
//   d_hat(mup,t') = mult[focc[mup] + t'] / A (= c_t' / c0)   =>  c_hat*d_hat exact.
// Stage-1 terms are grouped by m2 row (<=KPAD per group, spill-safe).
// Stage-2 is densified into D[i][mup].
// ---------------------------------------------------------------------------
__global__ void wigner_setup(const float* __restrict__ mult,
                             const int* __restrict__ m1,  const int* __restrict__ m1p,
                             const int* __restrict__ m2,  const int* __restrict__ m2p,
                             const int* __restrict__ mub, int n)
{
    __shared__ int focc[KOUT];
    __shared__ int sT[8];
    int tid = threadIdx.x;
    if (tid < KOUT) focc[tid] = 0x7fffffff;
    __syncthreads();
    for (int j = tid; j < n; j += blockDim.x)
        atomicMin(&focc[mub[j]], j);
    __syncthreads();
    if (tid == 0) {
        int T0 = focc[1] - focc[0];
        sT[0] = T0;
        for (int v = 1; v < 6; v++) sT[v] = focc[v + 1] - focc[v];
        int t6 = focc[7] / T0 - focc[6];
        sT[6] = t6;
        sT[7] = focc[6] + t6;                       // Ttot
        for (int v = 0; v < 7; v++) if (sT[v] > MAXT) sT[v] = MAXT;
    }
    // zero D while sT settles
    for (int i = tid; i < KOUT * 8; i += blockDim.x) g_D[i] = 0.0f;
    __syncthreads();

    float A = mult[0];
    int Ttot = sT[7];
    if (tid < 7) {
        int mu = tid;
        // zero this mu's group tables
        for (int g = 0; g < GMAX; g++) {
            g_ghdr[mu * GMAX + g] = X2BASE_B;
            for (int k = 0; k < KPAD; k++)
                g_gterm[(mu * GMAX + g) * KPAD + k] = make_uint2(0u, 0u);
        }
        // ---- stage-1 grouping by m2 row ----
        int r2of[GMAX], cnt[GMAX], G = 0;
        int T = sT[mu];
        int segbase = focc[mu * 7];
        for (int t = 0; t < T; t++) {
            int j = segbase + t * Ttot;             // (mu, t, mup=0, t'=0)
            int r1 = m1[j], r2 = m2[j];
            float c = mult[j];                      // = c_t * c0
            int g = -1;
            for (int q = 0; q < G; q++)
                if (r2of[q] == r2 && cnt[q] < KPAD) { g = q; break; }
            if (g < 0 && G < GMAX) {
                g = G++; r2of[g] = r2; cnt[g] = 0;
                g_ghdr[mu * GMAX + g] = (unsigned)(X2BASE_B + r2 * 32);
            }
            if (g >= 0) {
                g_gterm[(mu * GMAX + g) * KPAD + cnt[g]] =
                    make_uint2((unsigned)(r1 * 32), __float_as_uint(c));
                cnt[g]++;
            }
        }
        g_G[mu] = G;
        // ---- stage-2 densify: D[i][mup] ----
        for (int t = 0; t < sT[mu]; t++) {
            int j2 = focc[mu] + t;                  // (mu=0, t=0, mup=mu, t')
            int i = m1p[j2] * 7 + m2p[j2];
            g_D[i * 8 + mu] += mult[j2] / A;        // = c_t' / c0
        }
    }
}

// ---------------------------------------------------------------------------
// Main: thread = (sample, mu). Stage 1: m2-grouped rank-1 updates, X rows
// loaded as LDS.128 pairs (rows padded to 8 floats, lane stride 116 words
// -> conflict-free). Stage 2: dense D (compile-time W indices -> W stays in
// registers, no local spill, straight-line 441-instr FMA block).
// ---------------------------------------------------------------------------
__global__ void __launch_bounds__(THREADS_PER_BLK, 3)
wigner_main(const float* __restrict__ X1, const float* __restrict__ X2,
            float* __restrict__ out, int N)
{
    __shared__ float sm[SMEM_WORDS];
    __shared__ unsigned s_ghdr[7 * GMAX];
    __shared__ uint2    s_gterm[7 * GMAX * KPAD];
    __shared__ __align__(16) float s_D[KOUT * 8];
    __shared__ int s_G[8];

    int tid  = threadIdx.x;
    int lane = tid & 31;
    int mu   = tid >> 5;
    int base = blockIdx.x * SAMPLES_PER_BLK;
    int nvalid = N - base; if (nvalid > SAMPLES_PER_BLK) nvalid = SAMPLES_PER_BLK;

    const float* g1 = X1 + (size_t)base * KOUT;
    const float* g2 = X2 + (size_t)base * KOUT;

    if (nvalid == SAMPLES_PER_BLK) {
        // batched LDG (MLP=14) then table copies overlap the in-flight loads
        float r1v[7], r2v[7];
        #pragma unroll
        for (int k = 0; k < 7; k++) {
            int i = tid + k * THREADS_PER_BLK;
            r1v[k] = g1[i];
            r2v[k] = g2[i];
        }
        s_gterm[tid] = g_gterm[tid];
        s_gterm[tid + 224] = g_gterm[tid + 224];
        if (tid < 7 * GMAX) s_ghdr[tid] = g_ghdr[tid];
        s_D[tid] = g_D[tid];
        if (tid < KOUT * 8 - 224) s_D[tid + 224] = g_D[tid + 224];
        if (tid < 8) s_G[tid] = g_G[tid];
        #pragma unroll
        for (int k = 0; k < 7; k++) {
            int i = tid + k * THREADS_PER_BLK;
            int s = i / KOUT, c = i - s * KOUT;
            int r = c / 7,    a = c - r * 7;
            sm[s * XSTR + r * 8 + a]      = r1v[k];
            sm[s * XSTR + 56 + r * 8 + a] = r2v[k];
        }
    } else {
        s_gterm[tid] = g_gterm[tid];
        s_gterm[tid + 224] = g_gterm[tid + 224];
        if (tid < 7 * GMAX) s_ghdr[tid] = g_ghdr[tid];
        s_D[tid] = g_D[tid];
        if (tid < KOUT * 8 - 224) s_D[tid + 224] = g_D[tid + 224];
        if (tid < 8) s_G[tid] = g_G[tid];
        int total = nvalid * KOUT;
        for (int i = tid; i < total; i += THREADS_PER_BLK) {
            int s = i / KOUT, c = i - s * KOUT;
            int r = c / 7,    a = c - r * 7;
            sm[s * XSTR + r * 8 + a]      = g1[i];
            sm[s * XSTR + 56 + r * 8 + a] = g2[i];
        }
    }
    __syncthreads();

    if (lane < nvalid) {
        const char* xc = (const char*)(sm + lane * XSTR);

        // ---------------- stage 1 : grouped rank-1 updates -------------------
        float W[49];
        #pragma unroll
        for (int i = 0; i < 49; i++) W[i] = 0.0f;

        int G = s_G[mu];
        const unsigned* hdr = s_ghdr + mu * GMAX;
        const uint2*    gt  = s_gterm + mu * GMAX * KPAD;
        #pragma unroll 1
        for (int g = 0; g < G; g++) {
            unsigned h = hdr[g];
            float4 x2a = *(const float4*)(xc + h);
            float4 x2b = *(const float4*)(xc + h + 16);
            float u[7];
            #pragma unroll
            for (int a = 0; a < 7; a++) u[a] = 0.0f;
            #pragma unroll
            for (int k = 0; k < KPAD; k++) {
                uint2 tk = gt[g * KPAD + k];
                float c = __uint_as_float(tk.y);       // 0 for padding -> no-op
                float4 x1a = *(const float4*)(xc + tk.x);
                float4 x1b = *(const float4*)(xc + tk.x + 16);
                u[0] = fmaf(c, x1a.x, u[0]);
                u[1] = fmaf(c, x1a.y, u[1]);
                u[2] = fmaf(c, x1a.z, u[2]);
                u[3] = fmaf(c, x1a.w, u[3]);
                u[4] = fmaf(c, x1b.x, u[4]);
                u[5] = fmaf(c, x1b.y, u[5]);
                u[6] = fmaf(c, x1b.z, u[6]);
            }
            float x2v[7] = {x2a.x, x2a.y, x2a.z, x2a.w, x2b.x, x2b.y, x2b.z};
            #pragma unroll
            for (int a = 0; a < 7; a++) {
                #pragma unroll
                for (int b = 0; b < 7; b++)
                    W[a * 7 + b] = fmaf(u[a], x2v[b], W[a * 7 + b]);
            }
        }

        // ---------------- stage 2 : dense D, W stays in registers ------------
        float acc[7];
        #pragma unroll
        for (int q = 0; q < 7; q++) acc[q] = 0.0f;
        #pragma unroll
        for (int i = 0; i < 49; i++) {
            float4 d0 = *(const float4*)(s_D + i * 8);      // uniform -> broadcast
            float4 d1 = *(const float4*)(s_D + i * 8 + 4);
            float w = W[i];
            acc[0] = fmaf(d0.x, w, acc[0]);
            acc[1] = fmaf(d0.y, w, acc[1]);
            acc[2] = fmaf(d0.z, w, acc[2]);
            acc[3] = fmaf(d0.w, w, acc[3]);
            acc[4] = fmaf(d1.x, w, acc[4]);
            acc[5] = fmaf(d1.y, w, acc[5]);
            acc[6] = fmaf(d1.z, w, acc[6]);
        }

        // stage output transposed (stride 33 odd -> conflict-free)
        #pragma unroll
        for (int mup = 0; mup < 7; mup++)
            sm[OBASE + (mu * 7 + mup) * OUTSTR + lane] = acc[mup];
    }
    __syncthreads();

    // coalesced flush
    int total = nvalid * KOUT;
    float* go = out + (size_t)base * KOUT;
    for (int i = tid; i < total; i += THREADS_PER_BLK) {
        int s = i / KOUT, c = i - s * KOUT;
        go[i] = sm[OBASE + c * OUTSTR + s];
    }
}

// ---------------------------------------------------------------------------
extern "C" void kernel_launch(void* const* d_in, const int* in_sizes, int n_in,
                              void* d_out, int out_size)
{
    const float* X1   = (const float*)d_in[0];
    const float* X2   = (const float*)d_in[1];
    const float* mult = (const float*)d_in[2];
    const int*   m1   = (const int*)d_in[3];
    const int*   m1p  = (const int*)d_in[4];
    const int*   m2   = (const int*)d_in[5];
    const int*   m2p  = (const int*)d_in[6];
    const int*   mub  = (const int*)d_in[7];

    int n_aligned = in_sizes[2];
    int N = in_sizes[0] / KOUT;

    wigner_setup<<<1, 256>>>(mult, m1, m1p, m2, m2p, mub, n_aligned);

    int grid = (N + SAMPLES_PER_BLK - 1) / SAMPLES_PER_BLK;
    wigner_main<<<grid, THREADS_PER_BLK>>>(X1, X2, (float*)d_out, N);
}

// round 6
// speedup vs baseline: 1.4189x; 1.4189x over previous
#include <cuda_runtime.h>
#include <stdint.h>

#define KOUT 49
#define MAXT 32
#define SAMPLES_PER_BLK 32
#define THREADS_PER_BLK 224              // 7 warps: warp w -> mu = w, lane -> sample
#define XSTR 99                          // per-lane X blob: X1[0..48], X2[49..97], pad (odd -> conflict-free)
#define OBASE (SAMPLES_PER_BLK * XSTR)   // 3168 words
#define OUTSTR 33
#define SMEM_WORDS (OBASE + KOUT * OUTSTR)   // 4785 words = 19140 B

// ---- device tables built by setup kernel each launch ----
__device__ int   g_T[8];             // stage-1 term counts per mu
__device__ uint4 g_s1[7 * MAXT];     // stage1: {x1_row_byteoff, x2_row_byteoff, c bits, pad}
__device__ float g_D[KOUT * 8];      // dense stage-2: D[i][mup], i = m1p*7+m2p, row padded to 8

// ---------------------------------------------------------------------------
// Setup (fully parallel): recover factorized term lists from the aligned
// product arrays. Generation order is (mu, t, mup, t'):
//   focc[v] (v<7) -> start of (mu=0,t=0,mup=v) run ; focc[mu*7] -> mu segment
//   T[v] = focc[v+1]-focc[v] (v<6); T[6] = focc[7]/T[0] - focc[6]; Ttot = focc[6]+T[6]
// Coefficients from products only (A = mult[0] = c0^2):
//   c_hat(mu,t)   = mult[seg(mu) + t*Ttot]   (= c_t * c0)
//   d_hat(mup,t') = mult[focc[mup] + t'] / A (= c_t' / c0)   =>  c_hat*d_hat exact.
// Stage-2 is densified into D[i][mup] via atomicAdd (one thread per (mup,t')).
// ---------------------------------------------------------------------------
__global__ void wigner_setup(const float* __restrict__ mult,
                             const int* __restrict__ m1,  const int* __restrict__ m1p,
                             const int* __restrict__ m2,  const int* __restrict__ m2p,
                             const int* __restrict__ mub, int n)
{
    __shared__ int focc[KOUT];
    __shared__ int sT[8];
    int tid = threadIdx.x;
    if (tid < KOUT) focc[tid] = 0x7fffffff;
    // zero D (single block -> __syncthreads orders this before the atomics)
    for (int i = tid; i < KOUT * 8; i += blockDim.x) g_D[i] = 0.0f;
    __syncthreads();
    for (int j = tid; j < n; j += blockDim.x)
        atomicMin(&focc[mub[j]], j);
    __syncthreads();
    if (tid == 0) {
        int T0 = focc[1] - focc[0];
        sT[0] = T0;
        for (int v = 1; v < 6; v++) sT[v] = focc[v + 1] - focc[v];
        int t6 = focc[7] / T0 - focc[6];
        sT[6] = t6;
        sT[7] = focc[6] + t6;                       // Ttot
        for (int v = 0; v < 7; v++) if (sT[v] > MAXT) sT[v] = MAXT;
    }
    __syncthreads();
    if (tid < 8) g_T[tid] = sT[tid];
    float A = mult[0];
    int Ttot = sT[7];
    if (tid < 7 * MAXT) {
        int mu = tid >> 5, t = tid & 31;
        if (t < sT[mu]) {
            int j = focc[mu * 7] + t * Ttot;               // (mu, t, mup=0, t'=0)
            g_s1[tid] = make_uint4((unsigned)(m1[j] * 28),
                                   (unsigned)(196 + m2[j] * 28),
                                   __float_as_uint(mult[j]), 0u);
            int j2 = focc[mu] + t;                          // (mu=0, t=0, mup=mu, t')
            atomicAdd(&g_D[(m1p[j2] * 7 + m2p[j2]) * 8 + mu], mult[j2] / A);
        } else {
            g_s1[tid] = make_uint4(0u, 196u, 0u, 0u);       // pad: c=0 -> no-op
        }
    }
}

// ---------------------------------------------------------------------------
// Main: thread = (sample, mu). 7 warps/block, warp w -> mu = w, lane -> sample.
// Staging: all 14 LDG batched up-front (MLP=14, single DRAM wait).
// Stage 1: scalar per-term rank-1 update into register W[49] (double-buffered
// uniform table entry). Stage 2: dense D from shared (uniform broadcast
// LDS.128) with compile-time W indices -> W never leaves registers.
// ---------------------------------------------------------------------------
__global__ void __launch_bounds__(THREADS_PER_BLK, 4)
wigner_main(const float* __restrict__ X1, const float* __restrict__ X2,
            float* __restrict__ out, int N)
{
    __shared__ float sm[SMEM_WORDS];
    __shared__ uint4 s_s1[7 * MAXT];
    __shared__ __align__(16) float s_D[KOUT * 8];
    __shared__ int s_T[8];

    int tid  = threadIdx.x;
    int lane = tid & 31;
    int mu   = tid >> 5;
    int base = blockIdx.x * SAMPLES_PER_BLK;
    int nvalid = N - base; if (nvalid > SAMPLES_PER_BLK) nvalid = SAMPLES_PER_BLK;

    const float* g1 = X1 + (size_t)base * KOUT;
    const float* g2 = X2 + (size_t)base * KOUT;

    if (nvalid == SAMPLES_PER_BLK) {
        // batched LDG (MLP=14); table copies overlap the in-flight loads
        float r1v[7], r2v[7];
        #pragma unroll
        for (int k = 0; k < 7; k++) {
            int i = tid + k * THREADS_PER_BLK;
            r1v[k] = g1[i];
            r2v[k] = g2[i];
        }
        s_s1[tid] = g_s1[tid];
        s_D[tid] = g_D[tid];
        if (tid < KOUT * 8 - THREADS_PER_BLK) s_D[tid + THREADS_PER_BLK] = g_D[tid + THREADS_PER_BLK];
        if (tid < 8) s_T[tid] = g_T[tid];
        #pragma unroll
        for (int k = 0; k < 7; k++) {
            int i = tid + k * THREADS_PER_BLK;
            int s = i / KOUT;
            int c = i - s * KOUT;
            sm[s * XSTR + c]      = r1v[k];
            sm[s * XSTR + 49 + c] = r2v[k];
        }
    } else {
        s_s1[tid] = g_s1[tid];
        s_D[tid] = g_D[tid];
        if (tid < KOUT * 8 - THREADS_PER_BLK) s_D[tid + THREADS_PER_BLK] = g_D[tid + THREADS_PER_BLK];
        if (tid < 8) s_T[tid] = g_T[tid];
        int total = nvalid * KOUT;
        for (int i = tid; i < total; i += THREADS_PER_BLK) {
            int s = i / KOUT;
            int c = i - s * KOUT;
            sm[s * XSTR + c]      = g1[i];
            sm[s * XSTR + 49 + c] = g2[i];
        }
    }
    __syncthreads();

    if (lane < nvalid) {
        const char* xc = (const char*)(sm + lane * XSTR);

        // ---------------- stage 1 : W[49] in registers, single pass ----------
        float W[49];
        #pragma unroll
        for (int i = 0; i < 49; i++) W[i] = 0.0f;

        int Tmu = s_T[mu];
        const uint4* s1 = s_s1 + mu * MAXT;
        uint4 e = s1[0];                              // double-buffered table entry
        for (int t = 0; t < Tmu; t++) {
            uint4 en = s1[t + 1];                     // prefetch next (pad-safe)
            float c = __uint_as_float(e.z);
            const float* r1 = (const float*)(xc + e.x);
            const float* r2 = (const float*)(xc + e.y);
            float x2v[7];
            #pragma unroll
            for (int b = 0; b < 7; b++) x2v[b] = r2[b];
            #pragma unroll
            for (int a = 0; a < 7; a++) {
                float t1 = c * r1[a];
                #pragma unroll
                for (int b = 0; b < 7; b++)
                    W[a * 7 + b] = fmaf(t1, x2v[b], W[a * 7 + b]);
            }
            e = en;
        }

        // ---------------- stage 2 : dense D, W stays in registers ------------
        float acc[7];
        #pragma unroll
        for (int q = 0; q < 7; q++) acc[q] = 0.0f;
        #pragma unroll
        for (int i = 0; i < 49; i++) {
            float4 d0 = *(const float4*)(s_D + i * 8);      // uniform -> broadcast
            float4 d1 = *(const float4*)(s_D + i * 8 + 4);
            float w = W[i];
            acc[0] = fmaf(d0.x, w, acc[0]);
            acc[1] = fmaf(d0.y, w, acc[1]);
            acc[2] = fmaf(d0.z, w, acc[2]);
            acc[3] = fmaf(d0.w, w, acc[3]);
            acc[4] = fmaf(d1.x, w, acc[4]);
            acc[5] = fmaf(d1.y, w, acc[5]);
            acc[6] = fmaf(d1.z, w, acc[6]);
        }

        // stage output transposed (stride 33 odd -> conflict-free)
        #pragma unroll
        for (int mup = 0; mup < 7; mup++)
            sm[OBASE + (mu * 7 + mup) * OUTSTR + lane] = acc[mup];
    }
    __syncthreads();

    // coalesced flush (STG fire-and-forget)
    int total = nvalid * KOUT;
    float* go = out + (size_t)base * KOUT;
    for (int i = tid; i < total; i += THREADS_PER_BLK) {
        int s = i / KOUT;
        int c = i - s * KOUT;
        go[i] = sm[OBASE + c * OUTSTR + s];
    }
}

// ---------------------------------------------------------------------------
extern "C" void kernel_launch(void* const* d_in, const int* in_sizes, int n_in,
                              void* d_out, int out_size)
{
    const float* X1   = (const float*)d_in[0];
    const float* X2   = (const float*)d_in[1];
    const float* mult = (const float*)d_in[2];
    const int*   m1   = (const int*)d_in[3];
    const int*   m1p  = (const int*)d_in[4];
    const int*   m2   = (const int*)d_in[5];
    const int*   m2p  = (const int*)d_in[6];
    const int*   mub  = (const int*)d_in[7];

    int n_aligned = in_sizes[2];
    int N = in_sizes[0] / KOUT;

    wigner_setup<<<1, 256>>>(mult, m1, m1p, m2, m2p, mub, n_aligned);

    int grid = (N + SAMPLES_PER_BLK - 1) / SAMPLES_PER_BLK;
    wigner_main<<<grid, THREADS_PER_BLK>>>(X1, X2, (float*)d_out, N);
}